// round 8
// baseline (speedup 1.0000x reference)
#include <cuda_runtime.h>
#include <cuda_bf16.h>
#include <math.h>
#include <stdint.h>

#define BS_TOK 16384
#define DIM    1024
#define DDIM   4096
#define NEXP   8
#define KCAP   2048   // tokens per expert

// ---------------- scratch (device globals; allocation-free rule) ----------
__device__ __align__(16) __nv_bfloat16 g_w1[(size_t)NEXP * DDIM * DIM];  // 64MB
__device__ __align__(16) __nv_bfloat16 g_w2[(size_t)NEXP * DIM * DDIM];  // 64MB
__device__ __align__(16) __nv_bfloat16 g_Y [(size_t)BS_TOK * DIM];       // 32MB
__device__ __align__(16) __nv_bfloat16 g_H [(size_t)BS_TOK * DDIM];     // 128MB
__device__ __align__(16) float g_O[(size_t)BS_TOK * DIM];                // 64MB
__device__ float    g_scores[NEXP * BS_TOK];
__device__ unsigned g_keys  [NEXP * BS_TOK];
__device__ int      g_selidx[BS_TOK];
__device__ float    g_selw  [BS_TOK];
__device__ int      g_t2s   [BS_TOK * NEXP];   // token -> slot (or -1)

// ---------------- small helpers -------------------------------------------
__device__ __forceinline__ uint32_t smem_u32(const void* p) {
    uint32_t a;
    asm("{ .reg .u64 t; cvta.to.shared.u64 t, %1; cvt.u32.u64 %0, t; }"
        : "=r"(a) : "l"(p));
    return a;
}
template <int N>
__device__ __forceinline__ void cp_wait() {
    asm volatile("cp.async.wait_group %0;" :: "n"(N) : "memory");
}

// ---------------- weight conversion fp32 -> bf16 (both matrices) ----------
__global__ void convert_w_kernel(const float4* __restrict__ f1,
                                 const float4* __restrict__ f2) {
    size_t n = (size_t)NEXP * DDIM * DIM / 4;
    __nv_bfloat162* w1 = (__nv_bfloat162*)g_w1;
    __nv_bfloat162* w2 = (__nv_bfloat162*)g_w2;
    for (size_t i = (size_t)blockIdx.x * blockDim.x + threadIdx.x; i < n;
         i += (size_t)gridDim.x * blockDim.x) {
        float4 a = f1[i];
        w1[2*i]   = __floats2bfloat162_rn(a.x, a.y);
        w1[2*i+1] = __floats2bfloat162_rn(a.z, a.w);
        float4 b = f2[i];
        w2[2*i]   = __floats2bfloat162_rn(b.x, b.y);
        w2[2*i+1] = __floats2bfloat162_rn(b.z, b.w);
    }
}

// ---------------- gating: softmax(x @ gate_w^T), 2 tokens/block -----------
__global__ void gate_kernel(const float* __restrict__ x,
                            const float* __restrict__ gw) {
    int t0 = blockIdx.x * 2;
    int tid = threadIdx.x;
    const float4 x0 = ((const float4*)(x + (size_t)t0 * DIM))[tid];
    const float4 x1 = ((const float4*)(x + (size_t)(t0 + 1) * DIM))[tid];
    float a0[NEXP], a1[NEXP];
#pragma unroll
    for (int e = 0; e < NEXP; e++) {
        float4 wv = ((const float4*)(gw + (size_t)e * DIM))[tid];
        a0[e] = x0.x*wv.x + x0.y*wv.y + x0.z*wv.z + x0.w*wv.w;
        a1[e] = x1.x*wv.x + x1.y*wv.y + x1.z*wv.z + x1.w*wv.w;
    }
#pragma unroll
    for (int e = 0; e < NEXP; e++)
#pragma unroll
        for (int o = 16; o > 0; o >>= 1) {
            a0[e] += __shfl_xor_sync(0xffffffffu, a0[e], o);
            a1[e] += __shfl_xor_sync(0xffffffffu, a1[e], o);
        }

    __shared__ float sh[2][8][NEXP];
    __shared__ float lg[2][NEXP];
    int w = tid >> 5, l = tid & 31;
    if (l == 0)
#pragma unroll
        for (int e = 0; e < NEXP; e++) { sh[0][w][e] = a0[e]; sh[1][w][e] = a1[e]; }
    __syncthreads();
    if (tid < 16) {
        int tk = tid >> 3, e = tid & 7;
        float s = 0.f;
#pragma unroll
        for (int i = 0; i < 8; i++) s += sh[tk][i][e];
        lg[tk][e] = s;
    }
    __syncthreads();
    if (tid < 16) {
        int tk = tid >> 3, e = tid & 7;
        int t = t0 + tk;
        float mx = lg[tk][0];
#pragma unroll
        for (int i = 1; i < NEXP; i++) mx = fmaxf(mx, lg[tk][i]);
        float den = 0.f;
#pragma unroll
        for (int i = 0; i < NEXP; i++) den += expf(lg[tk][i] - mx);
        float sc = expf(lg[tk][e] - mx) / den;
        g_scores[e * BS_TOK + t] = sc;
        unsigned b = __float_as_uint(sc);
        b ^= (b >> 31) ? 0xFFFFFFFFu : 0x80000000u;
        g_keys[e * BS_TOK + t] = b;
    }
}

// ------- per-expert exact top-k: smem-cached keys, 8-bit radix select ------
#define TPK_T 1024
#define TPK_SMEM (BS_TOK * 4)    // 64KB dynamic: all keys of one expert

__global__ __launch_bounds__(TPK_T, 1) void topk_kernel() {
    extern __shared__ unsigned skeys[];          // [BS_TOK]
    __shared__ unsigned hist[256];
    __shared__ unsigned suf[256];
    __shared__ unsigned s_prefix;
    __shared__ int s_need, s_out;

    const int e = blockIdx.x;
    const int tid = threadIdx.x, lane = tid & 31;
    const unsigned* keys = g_keys + (size_t)e * BS_TOK;

#pragma unroll
    for (int i = 0; i < BS_TOK / (TPK_T * 4); i++) {
        uint4 v = ((const uint4*)keys)[tid + i * TPK_T];
        ((uint4*)skeys)[tid + i * TPK_T] = v;
    }
    if (tid == 0) { s_prefix = 0u; s_need = KCAP; s_out = 0; }
    __syncthreads();

#pragma unroll
    for (int p = 3; p >= 0; p--) {
        if (tid < 256) hist[tid] = 0u;
        __syncthreads();
        const int sh = p * 8;
        const unsigned maskHi = (p == 3) ? 0u : (0xFFFFFFFFu << ((p + 1) * 8));
        const unsigned pref = s_prefix;
        const int need = s_need;
#pragma unroll
        for (int i = 0; i < BS_TOK / TPK_T; i++) {
            unsigned k = skeys[tid + i * TPK_T];
            bool m = ((k & maskHi) == pref);
            unsigned bin = m ? ((k >> sh) & 255u) : 0xFFFFFFFFu;
            unsigned peers = __match_any_sync(0xffffffffu, bin);
            if (m && lane == (__ffs(peers) - 1))
                atomicAdd(&hist[bin], (unsigned)__popc(peers));
        }
        __syncthreads();
        if (tid < 256) suf[tid] = hist[tid];
        __syncthreads();
#pragma unroll
        for (int st = 1; st < 256; st <<= 1) {
            unsigned v = 0;
            if (tid < 256) v = suf[tid] + ((tid + st < 256) ? suf[tid + st] : 0u);
            __syncthreads();
            if (tid < 256) suf[tid] = v;
            __syncthreads();
        }
        if (tid < 256) {
            unsigned nxt = (tid == 255) ? 0u : suf[tid + 1];
            if ((int)suf[tid] >= need && (int)nxt < need) {
                s_prefix = pref | ((unsigned)tid << sh);
                s_need = need - (int)nxt;
            }
        }
        __syncthreads();
    }

    const unsigned T = s_prefix;
    const int needEq = s_need;
#pragma unroll
    for (int i = 0; i < BS_TOK / TPK_T; i++) {
        int t = tid + i * TPK_T;
        unsigned k = skeys[t];
        bool sel = false;
        if (k > T) sel = true;
        else if (k == T) {    // tie: lower index first (matches lax.top_k)
            int r = 0;
            for (int j = 0; j < t; j++) r += (skeys[j] == T);
            sel = (r < needEq);
        }
        if (sel) {
            int slot = atomicAdd(&s_out, 1);
            g_selidx[e * KCAP + slot] = t;
            g_selw  [e * KCAP + slot] = g_scores[(size_t)e * BS_TOK + t];
            g_t2s[t * NEXP + e] = e * KCAP + slot;
        }
    }
}

// ---------------- gather + layernorm -> bf16 Y (2 slots/block) ------------
__global__ void gather_ln_kernel(const float* __restrict__ x,
                                 const float* __restrict__ lnw,
                                 const float* __restrict__ lnb) {
    int g0 = blockIdx.x * 2;
    int tid = threadIdx.x;
    int tok0 = g_selidx[g0];
    int tok1 = g_selidx[g0 + 1];
    float4 v0 = ((const float4*)(x + (size_t)tok0 * DIM))[tid];
    float4 v1 = ((const float4*)(x + (size_t)tok1 * DIM))[tid];
    float s0 = v0.x + v0.y + v0.z + v0.w;
    float q0 = v0.x*v0.x + v0.y*v0.y + v0.z*v0.z + v0.w*v0.w;
    float s1 = v1.x + v1.y + v1.z + v1.w;
    float q1 = v1.x*v1.x + v1.y*v1.y + v1.z*v1.z + v1.w*v1.w;
#pragma unroll
    for (int o = 16; o > 0; o >>= 1) {
        s0 += __shfl_xor_sync(0xffffffffu, s0, o);
        q0 += __shfl_xor_sync(0xffffffffu, q0, o);
        s1 += __shfl_xor_sync(0xffffffffu, s1, o);
        q1 += __shfl_xor_sync(0xffffffffu, q1, o);
    }
    __shared__ float red[4][8];
    __shared__ float fin[4];
    int w = tid >> 5, l = tid & 31;
    if (l == 0) { red[0][w] = s0; red[1][w] = q0; red[2][w] = s1; red[3][w] = q1; }
    __syncthreads();
    if (tid < 2) {
        float S = 0.f, Q = 0.f;
#pragma unroll
        for (int i = 0; i < 8; i++) { S += red[2*tid][i]; Q += red[2*tid+1][i]; }
        float mu = S * (1.f / DIM);
        float var = Q * (1.f / DIM) - mu * mu;
        fin[2*tid]   = mu;
        fin[2*tid+1] = rsqrtf(var + 1e-5f);
    }
    __syncthreads();
    float mu0 = fin[0], rs0 = fin[1], mu1 = fin[2], rs1 = fin[3];
    float4 wv = ((const float4*)lnw)[tid];
    float4 bv = ((const float4*)lnb)[tid];
    __nv_bfloat162* y0 = (__nv_bfloat162*)(g_Y + (size_t)g0 * DIM);
    __nv_bfloat162* y1 = (__nv_bfloat162*)(g_Y + (size_t)(g0 + 1) * DIM);
    y0[tid*2]   = __floats2bfloat162_rn((v0.x-mu0)*rs0*wv.x + bv.x,
                                        (v0.y-mu0)*rs0*wv.y + bv.y);
    y0[tid*2+1] = __floats2bfloat162_rn((v0.z-mu0)*rs0*wv.z + bv.z,
                                        (v0.w-mu0)*rs0*wv.w + bv.w);
    y1[tid*2]   = __floats2bfloat162_rn((v1.x-mu1)*rs1*wv.x + bv.x,
                                        (v1.y-mu1)*rs1*wv.y + bv.y);
    y1[tid*2+1] = __floats2bfloat162_rn((v1.z-mu1)*rs1*wv.z + bv.z,
                                        (v1.w-mu1)*rs1*wv.w + bv.w);
}

// -------- mma.sync GEMM: BM x TBN x 64 tiles, 4-stage cp.async -------------
#define BM 128
#define BK 64
#define NSTG 4

__device__ __forceinline__ float gelu_f(float v) {
    float u = 0.7978845608028654f * (v + 0.044715f * v * v * v);
    float e = __expf(2.f * u);
    float th = 1.f - __fdividef(2.f, e + 1.f);
    return 0.5f * v * (1.f + th);
}

// EPI==1: g_H = gelu(Y @ W1^T + b1) bf16.   EPI==2: g_O[slot] = (acc+b2)*selw.
template <int EPI, int M, int N, int K, int TBN>
__global__ __launch_bounds__(256, 1) void mma_gemm(const float* __restrict__ bias) {
    constexpr int WTN  = TBN / 4;          // warp tile N (64 or 32)
    constexpr int NB   = WTN / 16;         // B ldmatrix.x4 per ks (4 or 2)
    constexpr int NI   = WTN / 8;          // mma n-steps (8 or 4)
    constexpr int STGB = (BM + TBN) * BK * 2;

    extern __shared__ __align__(1024) char smdyn[];
    const int tid = threadIdx.x, wid = tid >> 5, lane = tid & 31;
    const int wm = wid >> 2, wn = wid & 3;           // 2 x 4 warps
    const int e = blockIdx.z;
    uint32_t sb = smem_u32(smdyn);

    // CTA raster swizzle: walk 8 M-tiles fast, then N, for L2 reuse
    const int GX = N / TBN;
    int lin = blockIdx.y * GX + blockIdx.x;
    int bm, bn;
    {
        int inb = lin % (8 * GX);
        int g2 = lin / (8 * GX);
        bm = g2 * 8 + (inb & 7);
        bn = inb >> 3;
    }

    const __nv_bfloat16* A = ((EPI == 1) ? g_Y : g_H) +
                             ((size_t)e * M + (size_t)bm * BM) * (size_t)K;
    const __nv_bfloat16* B = ((EPI == 1) ? g_w1 : g_w2) +
                             ((size_t)e * N + (size_t)bn * TBN) * (size_t)K;

    __shared__ float bsm[TBN];
    if (tid < TBN) bsm[tid] = bias[(size_t)e * N + bn * TBN + tid];

    auto fill = [&](int c, int s) {
        uint32_t abase = sb + s * STGB;
        uint32_t bbase = abase + BM * BK * 2;     // +16KB
        const __nv_bfloat16* ga = A + c * BK;
        const __nv_bfloat16* gb = B + c * BK;
#pragma unroll
        for (int t = 0; t < 4; t++) {             // A: 1024 16B-chunks
            int i = tid + t * 256;
            int row = i >> 3, seg = i & 7;
            uint32_t off = (uint32_t)(row * 128 + seg * 16);
            off ^= (off >> 3) & 0x70u;
            asm volatile("cp.async.cg.shared.global [%0], [%1], 16;"
                         :: "r"(abase + off), "l"(ga + (size_t)row * K + seg * 8));
        }
#pragma unroll
        for (int t = 0; t < TBN / 32; t++) {      // B: TBN*8 16B-chunks
            int i = tid + t * 256;
            int row = i >> 3, seg = i & 7;
            uint32_t off = (uint32_t)(row * 128 + seg * 16);
            off ^= (off >> 3) & 0x70u;
            asm volatile("cp.async.cg.shared.global [%0], [%1], 16;"
                         :: "r"(bbase + off), "l"(gb + (size_t)row * K + seg * 8));
        }
        asm volatile("cp.async.commit_group;" ::: "memory");
    };

    float c[4][NI][4];
#pragma unroll
    for (int a = 0; a < 4; a++)
#pragma unroll
        for (int b = 0; b < NI; b++)
#pragma unroll
            for (int d = 0; d < 4; d++) c[a][b][d] = 0.f;

    const int nk = K / BK;
    fill(0, 0); fill(1, 1); fill(2, 2);

    for (int kc = 0; kc < nk; kc++) {
        int rem = nk - 1 - kc;
        if (rem >= 2) cp_wait<2>();
        else if (rem == 1) cp_wait<1>();
        else cp_wait<0>();
        __syncthreads();
        if (kc + 3 < nk) fill(kc + 3, (kc + 3) & 3);

        uint32_t abase = sb + (kc & 3) * STGB;
        uint32_t bbase = abase + BM * BK * 2;

#pragma unroll
        for (int ks = 0; ks < 4; ks++) {
            uint32_t a[4][4], b[NI][2];
            int ar = wm * 64 + (lane & 15);
            int ac = ks * 32 + (lane >> 4) * 16;
#pragma unroll
            for (int mi = 0; mi < 4; mi++) {
                uint32_t off = (uint32_t)((ar + mi * 16) * 128 + ac);
                off ^= (off >> 3) & 0x70u;
                asm volatile(
                    "ldmatrix.sync.aligned.m8n8.x4.shared.b16 {%0,%1,%2,%3}, [%4];"
                    : "=r"(a[mi][0]), "=r"(a[mi][1]), "=r"(a[mi][2]), "=r"(a[mi][3])
                    : "r"(abase + off));
            }
            int nr = wn * WTN + (lane & 7) + ((lane >> 4) << 3);
            int kb = ks * 32 + ((lane >> 3) & 1) * 16;
#pragma unroll
            for (int nb = 0; nb < NB; nb++) {
                uint32_t off = (uint32_t)((nr + nb * 16) * 128 + kb);
                off ^= (off >> 3) & 0x70u;
                asm volatile(
                    "ldmatrix.sync.aligned.m8n8.x4.shared.b16 {%0,%1,%2,%3}, [%4];"
                    : "=r"(b[2*nb][0]), "=r"(b[2*nb][1]),
                      "=r"(b[2*nb+1][0]), "=r"(b[2*nb+1][1])
                    : "r"(bbase + off));
            }
#pragma unroll
            for (int mi = 0; mi < 4; mi++)
#pragma unroll
                for (int ni = 0; ni < NI; ni++) {
                    asm volatile(
                        "mma.sync.aligned.m16n8k16.row.col.f32.bf16.bf16.f32 "
                        "{%0,%1,%2,%3}, {%4,%5,%6,%7}, {%8,%9}, {%0,%1,%2,%3};"
                        : "+f"(c[mi][ni][0]), "+f"(c[mi][ni][1]),
                          "+f"(c[mi][ni][2]), "+f"(c[mi][ni][3])
                        : "r"(a[mi][0]), "r"(a[mi][1]), "r"(a[mi][2]), "r"(a[mi][3]),
                          "r"(b[ni][0]), "r"(b[ni][1]));
                }
        }
        __syncthreads();
    }

    // -------- epilogue --------
    int g4 = lane >> 2, tg2 = (lane & 3) * 2;
    if (EPI == 1) {
#pragma unroll
        for (int mi = 0; mi < 4; mi++) {
            int row = bm * BM + wm * 64 + mi * 16 + g4;
            size_t h0 = ((size_t)e * M + row) * (size_t)N;
            size_t h1 = ((size_t)e * M + row + 8) * (size_t)N;
#pragma unroll
            for (int ni = 0; ni < NI; ni++) {
                int lc = wn * WTN + ni * 8 + tg2;
                int col = bn * TBN + lc;
                float bb0 = bsm[lc], bb1 = bsm[lc + 1];
                *(__nv_bfloat162*)(g_H + h0 + col) = __floats2bfloat162_rn(
                    gelu_f(c[mi][ni][0] + bb0), gelu_f(c[mi][ni][1] + bb1));
                *(__nv_bfloat162*)(g_H + h1 + col) = __floats2bfloat162_rn(
                    gelu_f(c[mi][ni][2] + bb0), gelu_f(c[mi][ni][3] + bb1));
            }
        }
    } else {
#pragma unroll
        for (int mi = 0; mi < 4; mi++) {
            int row = bm * BM + wm * 64 + mi * 16 + g4;
            float w0 = g_selw[e * KCAP + row];
            float w1 = g_selw[e * KCAP + row + 8];
            size_t o0 = ((size_t)e * M + row) * (size_t)N;
            size_t o1 = ((size_t)e * M + row + 8) * (size_t)N;
#pragma unroll
            for (int ni = 0; ni < NI; ni++) {
                int lc = wn * WTN + ni * 8 + tg2;
                int col = bn * TBN + lc;
                float bb0 = bsm[lc], bb1 = bsm[lc + 1];
                float2 v0 = make_float2((c[mi][ni][0] + bb0) * w0,
                                        (c[mi][ni][1] + bb1) * w0);
                float2 v1 = make_float2((c[mi][ni][2] + bb0) * w1,
                                        (c[mi][ni][3] + bb1) * w1);
                *(float2*)(g_O + o0 + col) = v0;
                *(float2*)(g_O + o1 + col) = v1;
            }
        }
    }
}

// ---------------- final combine (2 tokens/block) ---------------------------
__global__ void combine_kernel(const float* __restrict__ x,
                               float* __restrict__ out) {
    int t0 = blockIdx.x * 2;
    int t1 = t0 + 1;
    int j = threadIdx.x;
    __shared__ int sl[2][NEXP];
    if (j < NEXP) sl[0][j] = g_t2s[t0 * NEXP + j];
    else if (j < 2 * NEXP) sl[1][j - NEXP] = g_t2s[t1 * NEXP + (j - NEXP)];
    float4 a0 = ((const float4*)(x + (size_t)t0 * DIM))[j];
    float4 a1 = ((const float4*)(x + (size_t)t1 * DIM))[j];
    __syncthreads();
#pragma unroll
    for (int e = 0; e < NEXP; e++) {
        int s0 = sl[0][e], s1 = sl[1][e];
        if (s0 >= 0) {
            float4 o = ((const float4*)(g_O + (size_t)s0 * DIM))[j];
            a0.x += o.x; a0.y += o.y; a0.z += o.z; a0.w += o.w;
        }
        if (s1 >= 0) {
            float4 o = ((const float4*)(g_O + (size_t)s1 * DIM))[j];
            a1.x += o.x; a1.y += o.y; a1.z += o.z; a1.w += o.w;
        }
    }
    ((float4*)(out + (size_t)t0 * DIM))[j] = a0;
    ((float4*)(out + (size_t)t1 * DIM))[j] = a1;
}

// ---------------- launch ---------------------------------------------------
extern "C" void kernel_launch(void* const* d_in, const int* in_sizes, int n_in,
                              void* d_out, int out_size) {
    const float* x   = (const float*)d_in[0];
    const float* gw  = (const float*)d_in[1];
    const float* lnw = (const float*)d_in[2];
    const float* lnb = (const float*)d_in[3];
    const float* fc1 = (const float*)d_in[4];
    const float* b1  = (const float*)d_in[5];
    const float* fc2 = (const float*)d_in[6];
    const float* b2  = (const float*)d_in[7];
    float* out = (float*)d_out;

    constexpr int SMEM1 = NSTG * (BM + 256) * BK * 2;   // 196608
    constexpr int SMEM2 = NSTG * (BM + 128) * BK * 2;   // 131072
    cudaFuncSetAttribute(mma_gemm<1, KCAP, DDIM, DIM, 256>,
                         cudaFuncAttributeMaxDynamicSharedMemorySize, SMEM1);
    cudaFuncSetAttribute(mma_gemm<2, KCAP, DIM, DDIM, 128>,
                         cudaFuncAttributeMaxDynamicSharedMemorySize, SMEM2);
    cudaFuncSetAttribute(topk_kernel,
                         cudaFuncAttributeMaxDynamicSharedMemorySize, TPK_SMEM);

    void* t2sp = nullptr;
    cudaGetSymbolAddress(&t2sp, g_t2s);
    cudaMemsetAsync(t2sp, 0xFF, sizeof(int) * (size_t)BS_TOK * NEXP, 0);

    convert_w_kernel<<<4096, 256>>>((const float4*)fc1, (const float4*)fc2);
    gate_kernel<<<BS_TOK / 2, 256>>>(x, gw);
    topk_kernel<<<NEXP, TPK_T, TPK_SMEM>>>();
    gather_ln_kernel<<<BS_TOK / 2, 256>>>(x, lnw, lnb);

    {   // GEMM1: per expert (2048 x 4096 x 1024), tile 128x256 -> g_H
        dim3 grid(DDIM / 256, KCAP / BM, NEXP);   // (16, 16, 8)
        mma_gemm<1, KCAP, DDIM, DIM, 256><<<grid, 256, SMEM1>>>(b1);
    }
    {   // GEMM2: per expert (2048 x 1024 x 4096), tile 128x128 -> g_O
        dim3 grid(DIM / 128, KCAP / BM, NEXP);    // (8, 16, 8) = 1024 CTAs
        mma_gemm<2, KCAP, DIM, DDIM, 128><<<grid, 256, SMEM2>>>(b2);
    }
    combine_kernel<<<BS_TOK / 2, 256>>>(x, out);
}

// round 9
// speedup vs baseline: 1.0165x; 1.0165x over previous
#include <cuda_runtime.h>
#include <cuda_bf16.h>
#include <math.h>
#include <stdint.h>

#define BS_TOK 16384
#define DIM    1024
#define DDIM   4096
#define NEXP   8
#define KCAP   2048   // tokens per expert

// ---------------- scratch (device globals; allocation-free rule) ----------
__device__ __align__(16) __nv_bfloat16 g_w1[(size_t)NEXP * DDIM * DIM];  // 64MB
__device__ __align__(16) __nv_bfloat16 g_w2[(size_t)NEXP * DIM * DDIM];  // 64MB
__device__ __align__(16) __nv_bfloat16 g_Y [(size_t)BS_TOK * DIM];       // 32MB
__device__ __align__(16) __nv_bfloat16 g_H [(size_t)BS_TOK * DDIM];     // 128MB
__device__ __align__(16) float g_O[(size_t)BS_TOK * DIM];                // 64MB
__device__ float    g_scores[NEXP * BS_TOK];
__device__ unsigned g_keys  [NEXP * BS_TOK];
__device__ int      g_selidx[BS_TOK];
__device__ float    g_selw  [BS_TOK];
__device__ int      g_t2s   [BS_TOK * NEXP];   // token -> slot (or -1)

// ---------------- small helpers -------------------------------------------
__device__ __forceinline__ uint32_t smem_u32(const void* p) {
    uint32_t a;
    asm("{ .reg .u64 t; cvta.to.shared.u64 t, %1; cvt.u32.u64 %0, t; }"
        : "=r"(a) : "l"(p));
    return a;
}
template <int N>
__device__ __forceinline__ void cp_wait() {
    asm volatile("cp.async.wait_group %0;" :: "n"(N) : "memory");
}

// ---------------- weight conversion fp32 -> bf16 (both matrices) ----------
__global__ void convert_w_kernel(const float4* __restrict__ f1,
                                 const float4* __restrict__ f2) {
    size_t n = (size_t)NEXP * DDIM * DIM / 4;
    __nv_bfloat162* w1 = (__nv_bfloat162*)g_w1;
    __nv_bfloat162* w2 = (__nv_bfloat162*)g_w2;
    for (size_t i = (size_t)blockIdx.x * blockDim.x + threadIdx.x; i < n;
         i += (size_t)gridDim.x * blockDim.x) {
        float4 a = f1[i];
        w1[2*i]   = __floats2bfloat162_rn(a.x, a.y);
        w1[2*i+1] = __floats2bfloat162_rn(a.z, a.w);
        float4 b = f2[i];
        w2[2*i]   = __floats2bfloat162_rn(b.x, b.y);
        w2[2*i+1] = __floats2bfloat162_rn(b.z, b.w);
    }
}

// ---------------- gating: softmax(x @ gate_w^T), 2 tokens/block -----------
__global__ void gate_kernel(const float* __restrict__ x,
                            const float* __restrict__ gw) {
    int t0 = blockIdx.x * 2;
    int tid = threadIdx.x;
    // fold t2s init here (runs before topk writes it)
    if (tid < 2 * NEXP) g_t2s[t0 * NEXP + tid] = -1;
    const float4 x0 = ((const float4*)(x + (size_t)t0 * DIM))[tid];
    const float4 x1 = ((const float4*)(x + (size_t)(t0 + 1) * DIM))[tid];
    float a0[NEXP], a1[NEXP];
#pragma unroll
    for (int e = 0; e < NEXP; e++) {
        float4 wv = ((const float4*)(gw + (size_t)e * DIM))[tid];
        a0[e] = x0.x*wv.x + x0.y*wv.y + x0.z*wv.z + x0.w*wv.w;
        a1[e] = x1.x*wv.x + x1.y*wv.y + x1.z*wv.z + x1.w*wv.w;
    }
#pragma unroll
    for (int e = 0; e < NEXP; e++)
#pragma unroll
        for (int o = 16; o > 0; o >>= 1) {
            a0[e] += __shfl_xor_sync(0xffffffffu, a0[e], o);
            a1[e] += __shfl_xor_sync(0xffffffffu, a1[e], o);
        }

    __shared__ float sh[2][8][NEXP];
    __shared__ float lg[2][NEXP];
    int w = tid >> 5, l = tid & 31;
    if (l == 0)
#pragma unroll
        for (int e = 0; e < NEXP; e++) { sh[0][w][e] = a0[e]; sh[1][w][e] = a1[e]; }
    __syncthreads();
    if (tid < 16) {
        int tk = tid >> 3, e = tid & 7;
        float s = 0.f;
#pragma unroll
        for (int i = 0; i < 8; i++) s += sh[tk][i][e];
        lg[tk][e] = s;
    }
    __syncthreads();
    if (tid < 16) {
        int tk = tid >> 3, e = tid & 7;
        int t = t0 + tk;
        float mx = lg[tk][0];
#pragma unroll
        for (int i = 1; i < NEXP; i++) mx = fmaxf(mx, lg[tk][i]);
        float den = 0.f;
#pragma unroll
        for (int i = 0; i < NEXP; i++) den += expf(lg[tk][i] - mx);
        float sc = expf(lg[tk][e] - mx) / den;
        g_scores[e * BS_TOK + t] = sc;
        unsigned b = __float_as_uint(sc);
        b ^= (b >> 31) ? 0xFFFFFFFFu : 0x80000000u;
        g_keys[e * BS_TOK + t] = b;
    }
}

// ------- per-expert exact top-k: smem-cached keys, 8-bit radix select ------
#define TPK_T 1024
#define TPK_SMEM (BS_TOK * 4)    // 64KB dynamic: all keys of one expert

__global__ __launch_bounds__(TPK_T, 1) void topk_kernel() {
    extern __shared__ unsigned skeys[];          // [BS_TOK]
    __shared__ unsigned hist[256];
    __shared__ unsigned suf[256];
    __shared__ unsigned s_prefix;
    __shared__ int s_need, s_out;

    const int e = blockIdx.x;
    const int tid = threadIdx.x, lane = tid & 31;
    const unsigned* keys = g_keys + (size_t)e * BS_TOK;

#pragma unroll
    for (int i = 0; i < BS_TOK / (TPK_T * 4); i++) {
        uint4 v = ((const uint4*)keys)[tid + i * TPK_T];
        ((uint4*)skeys)[tid + i * TPK_T] = v;
    }
    if (tid == 0) { s_prefix = 0u; s_need = KCAP; s_out = 0; }
    __syncthreads();

#pragma unroll
    for (int p = 3; p >= 0; p--) {
        if (tid < 256) hist[tid] = 0u;
        __syncthreads();
        const int sh = p * 8;
        const unsigned maskHi = (p == 3) ? 0u : (0xFFFFFFFFu << ((p + 1) * 8));
        const unsigned pref = s_prefix;
        const int need = s_need;
#pragma unroll
        for (int i = 0; i < BS_TOK / TPK_T; i++) {
            unsigned k = skeys[tid + i * TPK_T];
            bool m = ((k & maskHi) == pref);
            unsigned bin = m ? ((k >> sh) & 255u) : 0xFFFFFFFFu;
            unsigned peers = __match_any_sync(0xffffffffu, bin);
            if (m && lane == (__ffs(peers) - 1))
                atomicAdd(&hist[bin], (unsigned)__popc(peers));
        }
        __syncthreads();
        if (tid < 256) suf[tid] = hist[tid];
        __syncthreads();
#pragma unroll
        for (int st = 1; st < 256; st <<= 1) {
            unsigned v = 0;
            if (tid < 256) v = suf[tid] + ((tid + st < 256) ? suf[tid + st] : 0u);
            __syncthreads();
            if (tid < 256) suf[tid] = v;
            __syncthreads();
        }
        if (tid < 256) {
            unsigned nxt = (tid == 255) ? 0u : suf[tid + 1];
            if ((int)suf[tid] >= need && (int)nxt < need) {
                s_prefix = pref | ((unsigned)tid << sh);
                s_need = need - (int)nxt;
            }
        }
        __syncthreads();
    }

    const unsigned T = s_prefix;
    const int needEq = s_need;
#pragma unroll
    for (int i = 0; i < BS_TOK / TPK_T; i++) {
        int t = tid + i * TPK_T;
        unsigned k = skeys[t];
        bool sel = false;
        if (k > T) sel = true;
        else if (k == T) {    // tie: lower index first (matches lax.top_k)
            int r = 0;
            for (int j = 0; j < t; j++) r += (skeys[j] == T);
            sel = (r < needEq);
        }
        if (sel) {
            int slot = atomicAdd(&s_out, 1);
            g_selidx[e * KCAP + slot] = t;
            g_selw  [e * KCAP + slot] = g_scores[(size_t)e * BS_TOK + t];
            g_t2s[t * NEXP + e] = e * KCAP + slot;
        }
    }
}

// ---------------- gather + layernorm -> bf16 Y (2 slots/block) ------------
__global__ void gather_ln_kernel(const float* __restrict__ x,
                                 const float* __restrict__ lnw,
                                 const float* __restrict__ lnb) {
    int g0 = blockIdx.x * 2;
    int tid = threadIdx.x;
    int tok0 = g_selidx[g0];
    int tok1 = g_selidx[g0 + 1];
    float4 v0 = ((const float4*)(x + (size_t)tok0 * DIM))[tid];
    float4 v1 = ((const float4*)(x + (size_t)tok1 * DIM))[tid];
    float s0 = v0.x + v0.y + v0.z + v0.w;
    float q0 = v0.x*v0.x + v0.y*v0.y + v0.z*v0.z + v0.w*v0.w;
    float s1 = v1.x + v1.y + v1.z + v1.w;
    float q1 = v1.x*v1.x + v1.y*v1.y + v1.z*v1.z + v1.w*v1.w;
#pragma unroll
    for (int o = 16; o > 0; o >>= 1) {
        s0 += __shfl_xor_sync(0xffffffffu, s0, o);
        q0 += __shfl_xor_sync(0xffffffffu, q0, o);
        s1 += __shfl_xor_sync(0xffffffffu, s1, o);
        q1 += __shfl_xor_sync(0xffffffffu, q1, o);
    }
    __shared__ float red[4][8];
    __shared__ float fin[4];
    int w = tid >> 5, l = tid & 31;
    if (l == 0) { red[0][w] = s0; red[1][w] = q0; red[2][w] = s1; red[3][w] = q1; }
    __syncthreads();
    if (tid < 2) {
        float S = 0.f, Q = 0.f;
#pragma unroll
        for (int i = 0; i < 8; i++) { S += red[2*tid][i]; Q += red[2*tid+1][i]; }
        float mu = S * (1.f / DIM);
        float var = Q * (1.f / DIM) - mu * mu;
        fin[2*tid]   = mu;
        fin[2*tid+1] = rsqrtf(var + 1e-5f);
    }
    __syncthreads();
    float mu0 = fin[0], rs0 = fin[1], mu1 = fin[2], rs1 = fin[3];
    float4 wv = ((const float4*)lnw)[tid];
    float4 bv = ((const float4*)lnb)[tid];
    __nv_bfloat162* y0 = (__nv_bfloat162*)(g_Y + (size_t)g0 * DIM);
    __nv_bfloat162* y1 = (__nv_bfloat162*)(g_Y + (size_t)(g0 + 1) * DIM);
    y0[tid*2]   = __floats2bfloat162_rn((v0.x-mu0)*rs0*wv.x + bv.x,
                                        (v0.y-mu0)*rs0*wv.y + bv.y);
    y0[tid*2+1] = __floats2bfloat162_rn((v0.z-mu0)*rs0*wv.z + bv.z,
                                        (v0.w-mu0)*rs0*wv.w + bv.w);
    y1[tid*2]   = __floats2bfloat162_rn((v1.x-mu1)*rs1*wv.x + bv.x,
                                        (v1.y-mu1)*rs1*wv.y + bv.y);
    y1[tid*2+1] = __floats2bfloat162_rn((v1.z-mu1)*rs1*wv.z + bv.z,
                                        (v1.w-mu1)*rs1*wv.w + bv.w);
}

// ---------------- mma.sync GEMM: 128x256x64 tiles, 4-stage cp.async --------
#define BM 128
#define BN 256
#define BK 64
#define NSTG 4
#define STGB ((BM + BN) * BK * 2)     // 49152 bytes per stage
#define GEMM_SMEM (NSTG * STGB)       // 196608

__device__ __forceinline__ float gelu_f(float v) {
    float u = 0.7978845608028654f * (v + 0.044715f * v * v * v);
    float e = __expf(2.f * u);
    float th = 1.f - __fdividef(2.f, e + 1.f);
    return 0.5f * v * (1.f + th);
}

// EPI==1: g_H = gelu(Y @ W1^T + b1) bf16.   EPI==2: g_O[slot] = (acc+b2)*selw.
template <int EPI, int M, int N, int K>
__global__ __launch_bounds__(256, 1) void mma_gemm(const float* __restrict__ bias) {
    extern __shared__ __align__(1024) char smdyn[];
    const int tid = threadIdx.x, wid = tid >> 5, lane = tid & 31;
    const int wm = wid >> 2, wn = wid & 3;           // 2 x 4 warps, 64x64 tiles
    const int e = blockIdx.z;
    uint32_t sb = smem_u32(smdyn);

    // CTA raster swizzle: walk 8 M-tiles fast, then N, for L2 reuse
    const int GX = N / BN;
    int lin = blockIdx.y * GX + blockIdx.x;
    int bm, bn;
    {
        int inb = lin % (8 * GX);
        int g2 = lin / (8 * GX);
        bm = g2 * 8 + (inb & 7);
        bn = inb >> 3;
    }

    const __nv_bfloat16* A = ((EPI == 1) ? g_Y : g_H) +
                             ((size_t)e * M + (size_t)bm * BM) * (size_t)K;
    const __nv_bfloat16* B = ((EPI == 1) ? g_w1 : g_w2) +
                             ((size_t)e * N + (size_t)bn * BN) * (size_t)K;

    __shared__ float bsm[BN];
    bsm[tid] = bias[(size_t)e * N + bn * BN + tid];

    auto fill = [&](int c, int s) {
        uint32_t abase = sb + s * STGB;
        uint32_t bbase = abase + BM * BK * 2;     // +16KB
        const __nv_bfloat16* ga = A + c * BK;
        const __nv_bfloat16* gb = B + c * BK;
#pragma unroll
        for (int t = 0; t < 4; t++) {
            int i = tid + t * 256;
            int row = i >> 3, seg = i & 7;
            uint32_t off = (uint32_t)(row * 128 + seg * 16);
            off ^= (off >> 3) & 0x70u;
            asm volatile("cp.async.cg.shared.global [%0], [%1], 16;"
                         :: "r"(abase + off), "l"(ga + (size_t)row * K + seg * 8));
        }
#pragma unroll
        for (int t = 0; t < 8; t++) {
            int i = tid + t * 256;
            int row = i >> 3, seg = i & 7;
            uint32_t off = (uint32_t)(row * 128 + seg * 16);
            off ^= (off >> 3) & 0x70u;
            asm volatile("cp.async.cg.shared.global [%0], [%1], 16;"
                         :: "r"(bbase + off), "l"(gb + (size_t)row * K + seg * 8));
        }
        asm volatile("cp.async.commit_group;" ::: "memory");
    };

    float c[4][8][4];
#pragma unroll
    for (int a = 0; a < 4; a++)
#pragma unroll
        for (int b = 0; b < 8; b++)
#pragma unroll
            for (int d = 0; d < 4; d++) c[a][b][d] = 0.f;

    const int nk = K / BK;
    fill(0, 0); fill(1, 1); fill(2, 2);

    for (int kc = 0; kc < nk; kc++) {
        int rem = nk - 1 - kc;
        if (rem >= 2) cp_wait<2>();
        else if (rem == 1) cp_wait<1>();
        else cp_wait<0>();
        __syncthreads();
        if (kc + 3 < nk) fill(kc + 3, (kc + 3) & 3);

        uint32_t abase = sb + (kc & 3) * STGB;
        uint32_t bbase = abase + BM * BK * 2;

#pragma unroll
        for (int ks = 0; ks < 4; ks++) {
            uint32_t a[4][4], b[8][2];
            int ar = wm * 64 + (lane & 15);
            int ac = ks * 32 + (lane >> 4) * 16;
#pragma unroll
            for (int mi = 0; mi < 4; mi++) {
                uint32_t off = (uint32_t)((ar + mi * 16) * 128 + ac);
                off ^= (off >> 3) & 0x70u;
                asm volatile(
                    "ldmatrix.sync.aligned.m8n8.x4.shared.b16 {%0,%1,%2,%3}, [%4];"
                    : "=r"(a[mi][0]), "=r"(a[mi][1]), "=r"(a[mi][2]), "=r"(a[mi][3])
                    : "r"(abase + off));
            }
            int nr = wn * 64 + (lane & 7) + ((lane >> 4) << 3);
            int kb = ks * 32 + ((lane >> 3) & 1) * 16;
#pragma unroll
            for (int nb = 0; nb < 4; nb++) {
                uint32_t off = (uint32_t)((nr + nb * 16) * 128 + kb);
                off ^= (off >> 3) & 0x70u;
                asm volatile(
                    "ldmatrix.sync.aligned.m8n8.x4.shared.b16 {%0,%1,%2,%3}, [%4];"
                    : "=r"(b[2*nb][0]), "=r"(b[2*nb][1]),
                      "=r"(b[2*nb+1][0]), "=r"(b[2*nb+1][1])
                    : "r"(bbase + off));
            }
#pragma unroll
            for (int mi = 0; mi < 4; mi++)
#pragma unroll
                for (int ni = 0; ni < 8; ni++) {
                    asm volatile(
                        "mma.sync.aligned.m16n8k16.row.col.f32.bf16.bf16.f32 "
                        "{%0,%1,%2,%3}, {%4,%5,%6,%7}, {%8,%9}, {%0,%1,%2,%3};"
                        : "+f"(c[mi][ni][0]), "+f"(c[mi][ni][1]),
                          "+f"(c[mi][ni][2]), "+f"(c[mi][ni][3])
                        : "r"(a[mi][0]), "r"(a[mi][1]), "r"(a[mi][2]), "r"(a[mi][3]),
                          "r"(b[ni][0]), "r"(b[ni][1]));
                }
        }
        __syncthreads();
    }

    // -------- epilogue --------
    int g4 = lane >> 2, tg2 = (lane & 3) * 2;
    if (EPI == 1) {
#pragma unroll
        for (int mi = 0; mi < 4; mi++) {
            int row = bm * BM + wm * 64 + mi * 16 + g4;
            size_t h0 = ((size_t)e * M + row) * (size_t)N;
            size_t h1 = ((size_t)e * M + row + 8) * (size_t)N;
#pragma unroll
            for (int ni = 0; ni < 8; ni++) {
                int lc = wn * 64 + ni * 8 + tg2;
                int col = bn * BN + lc;
                float bb0 = bsm[lc], bb1 = bsm[lc + 1];
                *(__nv_bfloat162*)(g_H + h0 + col) = __floats2bfloat162_rn(
                    gelu_f(c[mi][ni][0] + bb0), gelu_f(c[mi][ni][1] + bb1));
                *(__nv_bfloat162*)(g_H + h1 + col) = __floats2bfloat162_rn(
                    gelu_f(c[mi][ni][2] + bb0), gelu_f(c[mi][ni][3] + bb1));
            }
        }
    } else {
#pragma unroll
        for (int mi = 0; mi < 4; mi++) {
            int row = bm * BM + wm * 64 + mi * 16 + g4;
            float w0 = g_selw[e * KCAP + row];
            float w1 = g_selw[e * KCAP + row + 8];
            size_t o0 = ((size_t)e * M + row) * (size_t)N;
            size_t o1 = ((size_t)e * M + row + 8) * (size_t)N;
#pragma unroll
            for (int ni = 0; ni < 8; ni++) {
                int lc = wn * 64 + ni * 8 + tg2;
                int col = bn * BN + lc;
                float bb0 = bsm[lc], bb1 = bsm[lc + 1];
                float2 v0 = make_float2((c[mi][ni][0] + bb0) * w0,
                                        (c[mi][ni][1] + bb1) * w0);
                float2 v1 = make_float2((c[mi][ni][2] + bb0) * w1,
                                        (c[mi][ni][3] + bb1) * w1);
                *(float2*)(g_O + o0 + col) = v0;
                *(float2*)(g_O + o1 + col) = v1;
            }
        }
    }
}

// ---------------- final combine (2 tokens/block) ---------------------------
__global__ void combine_kernel(const float* __restrict__ x,
                               float* __restrict__ out) {
    int t0 = blockIdx.x * 2;
    int t1 = t0 + 1;
    int j = threadIdx.x;
    __shared__ int sl[2][NEXP];
    if (j < NEXP) sl[0][j] = g_t2s[t0 * NEXP + j];
    else if (j < 2 * NEXP) sl[1][j - NEXP] = g_t2s[t1 * NEXP + (j - NEXP)];
    float4 a0 = ((const float4*)(x + (size_t)t0 * DIM))[j];
    float4 a1 = ((const float4*)(x + (size_t)t1 * DIM))[j];
    __syncthreads();
#pragma unroll
    for (int e = 0; e < NEXP; e++) {
        int s0 = sl[0][e], s1 = sl[1][e];
        if (s0 >= 0) {
            float4 o = ((const float4*)(g_O + (size_t)s0 * DIM))[j];
            a0.x += o.x; a0.y += o.y; a0.z += o.z; a0.w += o.w;
        }
        if (s1 >= 0) {
            float4 o = ((const float4*)(g_O + (size_t)s1 * DIM))[j];
            a1.x += o.x; a1.y += o.y; a1.z += o.z; a1.w += o.w;
        }
    }
    ((float4*)(out + (size_t)t0 * DIM))[j] = a0;
    ((float4*)(out + (size_t)t1 * DIM))[j] = a1;
}

// ---------------- launch ---------------------------------------------------
extern "C" void kernel_launch(void* const* d_in, const int* in_sizes, int n_in,
                              void* d_out, int out_size) {
    const float* x   = (const float*)d_in[0];
    const float* gw  = (const float*)d_in[1];
    const float* lnw = (const float*)d_in[2];
    const float* lnb = (const float*)d_in[3];
    const float* fc1 = (const float*)d_in[4];
    const float* b1  = (const float*)d_in[5];
    const float* fc2 = (const float*)d_in[6];
    const float* b2  = (const float*)d_in[7];
    float* out = (float*)d_out;

    cudaFuncSetAttribute(mma_gemm<1, KCAP, DDIM, DIM>,
                         cudaFuncAttributeMaxDynamicSharedMemorySize, GEMM_SMEM);
    cudaFuncSetAttribute(mma_gemm<2, KCAP, DIM, DDIM>,
                         cudaFuncAttributeMaxDynamicSharedMemorySize, GEMM_SMEM);
    cudaFuncSetAttribute(topk_kernel,
                         cudaFuncAttributeMaxDynamicSharedMemorySize, TPK_SMEM);

    // fork: convert_w (DRAM-bound, ~56us) runs on side stream, fully
    // concurrent with the routing chain (compute/latency-bound, ~55us,
    // topk uses only 8 SMs). Join before GEMM1.
    cudaStream_t sB;
    cudaStreamCreateWithFlags(&sB, cudaStreamNonBlocking);
    cudaEvent_t evFork, evW;
    cudaEventCreateWithFlags(&evFork, cudaEventDisableTiming);
    cudaEventCreateWithFlags(&evW,    cudaEventDisableTiming);

    cudaEventRecord(evFork, 0);
    cudaStreamWaitEvent(sB, evFork, 0);
    convert_w_kernel<<<4096, 256, 0, sB>>>((const float4*)fc1,
                                           (const float4*)fc2);
    cudaEventRecord(evW, sB);

    gate_kernel<<<BS_TOK / 2, 256>>>(x, gw);          // also inits g_t2s
    topk_kernel<<<NEXP, TPK_T, TPK_SMEM>>>();
    gather_ln_kernel<<<BS_TOK / 2, 256>>>(x, lnw, lnb);

    cudaStreamWaitEvent(0, evW, 0);                   // join: weights ready
    {   // GEMM1: per expert (2048 x 4096 x 1024), fused bias + gelu -> g_H
        dim3 grid(DDIM / BN, KCAP / BM, NEXP);   // (16, 16, 8)
        mma_gemm<1, KCAP, DDIM, DIM><<<grid, 256, GEMM_SMEM>>>(b1);
    }
    {   // GEMM2: per expert (2048 x 1024 x 4096), fused bias + gate scale -> g_O
        dim3 grid(DIM / BN, KCAP / BM, NEXP);    // (4, 16, 8)
        mma_gemm<2, KCAP, DIM, DDIM><<<grid, 256, GEMM_SMEM>>>(b2);
    }
    combine_kernel<<<BS_TOK / 2, 256>>>(x, out);
}